// round 12
// baseline (speedup 1.0000x reference)
#include <cuda_runtime.h>
#include <cstdint>

// ---------------------------------------------------------------------------
// GIN: 3 layers of { rst = h + segment_sum(h[src], dst); h = MLP2(rst) }
// N=100000, E=1600000, D=128.
//   - CSR build (3 launches): hist, single-block scan, fill(+deg re-zero)
//   - PERSISTENT fused layer kernel, 1 block/SM, 512 threads:
//       warps 0-3   = producers: gather tile (96 rows) into double buffer
//       warps 4-15  = consumers: FFMA2 (fma.rn.f32x2) 2-GEMM MLP,
//                     micro-tile 8 rows x 4 cols (A warp-broadcast loads)
//     Named-barrier full/empty handshake; W1+W2 resident in smem.
//   - Last layer folded: W12 = W1@W2, b12 = b1@W2 + b2 (no relu anywhere).
// ---------------------------------------------------------------------------

#define DIM 128
#define MAXN 100000
#define MAXE 1600000
#define TILE_M 96
#define SA_PITCH 128
#define N_PROD 128
#define N_CONS 384
#define SMEM_FLOATS (2 * 16384 + 2 * TILE_M * SA_PITCH)
#define SMEM_BYTES (SMEM_FLOATS * 4)     // 229376 B = 224 KB

#define BAR_FULL0  1
#define BAR_FULL1  2
#define BAR_EMPTY0 3
#define BAR_EMPTY1 4
#define BAR_CONS   5

typedef unsigned long long u64;

// scratch (device globals: no allocation allowed; zero-initialized at load)
__device__ int   g_deg[MAXN];
__device__ int   g_rowptr[MAXN + 1];
__device__ int   g_cursor[MAXN];
__device__ int   g_col[MAXE];
__device__ __align__(16) float g_hA [(size_t)MAXN * DIM];
__device__ __align__(16) float g_hB [(size_t)MAXN * DIM];
__device__ __align__(16) float g_W12[DIM * DIM];
__device__ __align__(16) float g_b12[DIM];

// ------------------------- helpers ------------------------------------------

__device__ __forceinline__ u64 pack2(float x, float y) {
    u64 r;
    asm("mov.b64 %0, {%1, %2};" : "=l"(r) : "f"(x), "f"(y));
    return r;
}
__device__ __forceinline__ void unpack2(u64 v, float& x, float& y) {
    asm("mov.b64 {%0, %1}, %2;" : "=f"(x), "=f"(y) : "l"(v));
}
__device__ __forceinline__ void fma2(u64& d, u64 a, u64 b) {
    asm("fma.rn.f32x2 %0, %1, %2, %0;" : "+l"(d) : "l"(a), "l"(b));
}
__device__ __forceinline__ void bar_sync(int id, int cnt) {
    asm volatile("bar.sync %0, %1;" :: "r"(id), "r"(cnt) : "memory");
}
__device__ __forceinline__ void bar_arrive(int id, int cnt) {
    asm volatile("bar.arrive %0, %1;" :: "r"(id), "r"(cnt) : "memory");
}

// -------------------------- CSR build ---------------------------------------

__global__ void k_hist(const int* __restrict__ dst, int e) {
    int i = blockIdx.x * blockDim.x + threadIdx.x;
    if (i < e) atomicAdd(&g_deg[dst[i]], 1);
}

__global__ void __launch_bounds__(1024) k_scan1(int n, int e) {
    __shared__ int s[1024];
    const int tid = threadIdx.x;
    int carry = 0;
    const int CH = 1024 * 8;
    for (int base = 0; base < n; base += CH) {
        int v[8];
        int run = 0;
#pragma unroll
        for (int j = 0; j < 8; ++j) {
            int idx = base + tid * 8 + j;
            int t = (idx < n) ? g_deg[idx] : 0;
            v[j] = run;
            run += t;
        }
        s[tid] = run;
        __syncthreads();
        int tot = run;
        for (int off = 1; off < 1024; off <<= 1) {
            int add = (tid >= off) ? s[tid - off] : 0;
            __syncthreads();
            s[tid] += add;
            __syncthreads();
        }
        int excl = carry + s[tid] - tot;
#pragma unroll
        for (int j = 0; j < 8; ++j) {
            int idx = base + tid * 8 + j;
            if (idx < n) {
                int r = excl + v[j];
                g_rowptr[idx] = r;
                g_cursor[idx] = r;
            }
        }
        carry += s[1023];
        __syncthreads();
    }
    if (tid == 0) g_rowptr[n] = e;
}

__global__ void k_fill(const int* __restrict__ src, const int* __restrict__ dst,
                       int e, int n) {
    int i = blockIdx.x * blockDim.x + threadIdx.x;
    if (i < n) g_deg[i] = 0;     // re-zero for next graph replay
    if (i < e) {
        int d = dst[i];
        int pos = atomicAdd(&g_cursor[d], 1);
        g_col[pos] = src[i];
    }
}

// -------------------- last-layer weight folding ------------------------------

__global__ void k_wbfuse(const float* __restrict__ W1g, const float* __restrict__ W2g,
                         const float* __restrict__ b1g, const float* __restrict__ b2g) {
    __shared__ float row[128];
    int nn = threadIdx.x;
    if (blockIdx.x < 128) {
        int k = blockIdx.x;
        row[nn] = W1g[k * 128 + nn];
        __syncthreads();
        float acc = 0.f;
#pragma unroll 8
        for (int j = 0; j < 128; ++j) acc += row[j] * W2g[j * 128 + nn];
        g_W12[k * 128 + nn] = acc;
    } else {
        row[nn] = b1g[nn];
        __syncthreads();
        float acc = b2g[nn];
#pragma unroll 8
        for (int j = 0; j < 128; ++j) acc += row[j] * W2g[j * 128 + nn];
        g_b12[nn] = acc;
    }
}

// ---------------------- consumer GEMM phase ----------------------------------
// 96x128x128, 384 consumer threads, micro-tile 8 rows x 4 cols.
// A loads are warp-broadcast (whole warp shares one row); W loads contiguous.

__device__ __forceinline__ void gemm96(const float* __restrict__ sA,
                                       const float* __restrict__ sW,
                                       const u64 bb[2], int r0, int c0,
                                       u64 acc[8][2]) {
#pragma unroll
    for (int i = 0; i < 8; ++i) { acc[i][0] = bb[0]; acc[i][1] = bb[1]; }
#pragma unroll 1
    for (int k0 = 0; k0 < 128; k0 += 4) {
        float4 a4[8];
#pragma unroll
        for (int i = 0; i < 8; ++i)
            a4[i] = *(const float4*)&sA[(r0 + i) * SA_PITCH + k0];
#pragma unroll
        for (int kk = 0; kk < 4; ++kk) {
            ulonglong2 w = *(const ulonglong2*)&sW[(k0 + kk) * 128 + c0];
#pragma unroll
            for (int i = 0; i < 8; ++i) {
                float av = ((const float*)&a4[i])[kk];
                u64 aa = pack2(av, av);
                fma2(acc[i][0], aa, w.x);
                fma2(acc[i][1], aa, w.y);
            }
        }
    }
}

// ---------------------- persistent fused layer -------------------------------
// LAST=false: out = relu( relu(A@W1+b1) @ W2 + b2 )
// LAST=true : out = A@W1+b1   (folded W12/b12)

template <bool LAST>
__global__ void __launch_bounds__(512, 1)
k_gin(const float* __restrict__ hin,
      const float* __restrict__ W1g, const float* __restrict__ b1g,
      const float* __restrict__ W2g, const float* __restrict__ b2g,
      float* __restrict__ out, int n, int T) {
    extern __shared__ float smem[];
    float* sW1 = smem;             // 16384
    float* sW2 = smem + 16384;     // 16384
    float* sAb = smem + 32768;     // 2 * 96*128

    const int tid = threadIdx.x;
    const int G = gridDim.x;

    // load weights once (all 512 threads)
    {
        const float4* w4 = (const float4*)W1g;
        float4* s4 = (float4*)sW1;
#pragma unroll
        for (int it = 0; it < 8; ++it) s4[tid + it * 512] = w4[tid + it * 512];
        if (!LAST) {
            const float4* v4 = (const float4*)W2g;
            float4* t4 = (float4*)sW2;
#pragma unroll
            for (int it = 0; it < 8; ++it) t4[tid + it * 512] = v4[tid + it * 512];
        }
    }
    __syncthreads();

    if (tid < N_PROD) {
        // ================= producer: 4 warps, 24 rows each ==================
        const int wid = tid >> 5, lane = tid & 31;
        const float4* __restrict__ h4 = (const float4*)hin;
        int s = 0;
        for (int t = blockIdx.x; t < T; t += G, ++s) {
            const int buf = s & 1;
            if (s >= 2) bar_sync(BAR_EMPTY0 + buf, 512);
            float* sA = sAb + buf * (TILE_M * SA_PITCH);
            const int row0 = t * TILE_M;
#pragma unroll 1
            for (int rr = 0; rr < 24; ++rr) {
                int r  = wid * 24 + rr;
                int rg = row0 + r;
                float4 a = make_float4(0.f, 0.f, 0.f, 0.f);
                if (rg < n) {
                    a = h4[(size_t)rg * 32 + lane];   // self, (1+eps)=1
                    int i = g_rowptr[rg];
                    const int epos = g_rowptr[rg + 1];
                    for (; i + 4 <= epos; i += 4) {
                        int s0 = g_col[i],     s1 = g_col[i + 1];
                        int s2 = g_col[i + 2], s3 = g_col[i + 3];
                        float4 v0 = __ldg(&h4[(size_t)s0 * 32 + lane]);
                        float4 v1 = __ldg(&h4[(size_t)s1 * 32 + lane]);
                        float4 v2 = __ldg(&h4[(size_t)s2 * 32 + lane]);
                        float4 v3 = __ldg(&h4[(size_t)s3 * 32 + lane]);
                        a.x += (v0.x + v1.x) + (v2.x + v3.x);
                        a.y += (v0.y + v1.y) + (v2.y + v3.y);
                        a.z += (v0.z + v1.z) + (v2.z + v3.z);
                        a.w += (v0.w + v1.w) + (v2.w + v3.w);
                    }
                    for (; i < epos; ++i) {
                        int sn = g_col[i];
                        float4 v = __ldg(&h4[(size_t)sn * 32 + lane]);
                        a.x += v.x; a.y += v.y; a.z += v.z; a.w += v.w;
                    }
                }
                *(float4*)&sA[r * SA_PITCH + lane * 4] = a;
            }
            __threadfence_block();
            bar_arrive(BAR_FULL0 + buf, 512);
        }
    } else {
        // ================= consumer: 12 warps, 2-GEMM MLP ===================
        const int tc   = tid - N_PROD;  // 0..383
        const int trow = tc >> 5;       // 0..11 -> rows trow*8..+7
        const int tcol = tc & 31;       // 0..31 -> cols tcol*4..+3
        const int r0 = trow * 8, c0 = tcol * 4;

        u64 bb1[2], bb2[2];
        {
            float4 x = *(const float4*)&b1g[c0];
            bb1[0] = pack2(x.x, x.y); bb1[1] = pack2(x.z, x.w);
            if (!LAST) {
                float4 u = *(const float4*)&b2g[c0];
                bb2[0] = pack2(u.x, u.y); bb2[1] = pack2(u.z, u.w);
            }
        }

        int s = 0;
        for (int t = blockIdx.x; t < T; t += G, ++s) {
            const int buf = s & 1;
            bar_sync(BAR_FULL0 + buf, 512);
            float* sA = sAb + buf * (TILE_M * SA_PITCH);
            const int row0 = t * TILE_M;

            u64 acc[8][2];
            gemm96(sA, sW1, bb1, r0, c0, acc);

            if (!LAST) {
                bar_sync(BAR_CONS, N_CONS);    // consumers done reading A
#pragma unroll
                for (int i = 0; i < 8; ++i) {
                    float x0, y0, x1, y1;
                    unpack2(acc[i][0], x0, y0);
                    unpack2(acc[i][1], x1, y1);
                    x0 = fmaxf(x0, 0.f); y0 = fmaxf(y0, 0.f);
                    x1 = fmaxf(x1, 0.f); y1 = fmaxf(y1, 0.f);
                    *(u64*)&sA[(r0 + i) * SA_PITCH + c0]     = pack2(x0, y0);
                    *(u64*)&sA[(r0 + i) * SA_PITCH + c0 + 2] = pack2(x1, y1);
                }
                bar_sync(BAR_CONS, N_CONS);    // h1 visible to all consumers

                u64 acc2[8][2];
                gemm96(sA, sW2, bb2, r0, c0, acc2);
                bar_arrive(BAR_EMPTY0 + buf, 512);   // buffer free

#pragma unroll
                for (int i = 0; i < 8; ++i) {
                    int rg = row0 + r0 + i;
                    if (rg < n) {
                        float x0, y0, x1, y1;
                        unpack2(acc2[i][0], x0, y0);
                        unpack2(acc2[i][1], x1, y1);
                        x0 = fmaxf(x0, 0.f); y0 = fmaxf(y0, 0.f);
                        x1 = fmaxf(x1, 0.f); y1 = fmaxf(y1, 0.f);
                        *(float4*)&out[(size_t)rg * 128 + c0] =
                            make_float4(x0, y0, x1, y1);
                    }
                }
            } else {
                bar_arrive(BAR_EMPTY0 + buf, 512);
#pragma unroll
                for (int i = 0; i < 8; ++i) {
                    int rg = row0 + r0 + i;
                    if (rg < n) {
                        float x0, y0, x1, y1;
                        unpack2(acc[i][0], x0, y0);
                        unpack2(acc[i][1], x1, y1);
                        *(float4*)&out[(size_t)rg * 128 + c0] =
                            make_float4(x0, y0, x1, y1);
                    }
                }
            }
        }
    }
}

// ---------------------------- host ------------------------------------------

extern "C" void kernel_launch(void* const* d_in, const int* in_sizes, int n_in,
                              void* d_out, int out_size) {
    const float* feat = (const float*)d_in[0];
    const float* W1   = (const float*)d_in[1];
    const float* b1   = (const float*)d_in[2];
    const float* W2   = (const float*)d_in[3];
    const float* b2   = (const float*)d_in[4];
    const int*   src  = (const int*)d_in[5];
    const int*   dst  = (const int*)d_in[6];

    const int n = in_sizes[0] / DIM;
    const int e = in_sizes[5];

    cudaFuncSetAttribute((const void*)k_gin<false>,
                         cudaFuncAttributeMaxDynamicSharedMemorySize, SMEM_BYTES);
    cudaFuncSetAttribute((const void*)k_gin<true>,
                         cudaFuncAttributeMaxDynamicSharedMemorySize, SMEM_BYTES);

    int G = 148;
    cudaDeviceGetAttribute(&G, cudaDevAttrMultiProcessorCount, 0);

    float *hA, *hB, *w12, *b12;
    cudaGetSymbolAddress((void**)&hA,  g_hA);
    cudaGetSymbolAddress((void**)&hB,  g_hB);
    cudaGetSymbolAddress((void**)&w12, g_W12);
    cudaGetSymbolAddress((void**)&b12, g_b12);

    const int T = (n + TILE_M - 1) / TILE_M;

    // ---- CSR build ----
    k_hist<<<(e + 255) / 256, 256>>>(dst, e);                 // launch 0
    k_scan1<<<1, 1024>>>(n, e);                               // launch 1
    k_fill<<<(e + 255) / 256, 256>>>(src, dst, e, n);         // launch 2

    // ---- layer 0 ----                                        launch 3
    k_gin<false><<<G, 512, SMEM_BYTES>>>(
        feat, W1 + 0 * DIM * DIM, b1 + 0 * DIM, W2 + 0 * DIM * DIM, b2 + 0 * DIM,
        hA, n, T);
    // ---- layer 1 ----                                        launch 4
    k_gin<false><<<G, 512, SMEM_BYTES>>>(
        hA, W1 + 1 * DIM * DIM, b1 + 1 * DIM, W2 + 1 * DIM * DIM, b2 + 1 * DIM,
        hB, n, T);
    // ---- fold last-layer weights ----                        launch 5
    k_wbfuse<<<129, 128>>>(W1 + 2 * DIM * DIM, W2 + 2 * DIM * DIM,
                           b1 + 2 * DIM, b2 + 2 * DIM);
    // ---- layer 2 (folded single GEMM, no relu) ----          launch 6
    k_gin<true><<<G, 512, SMEM_BYTES>>>(
        hB, w12, b12, nullptr, nullptr, (float*)d_out, n, T);
}

// round 13
// speedup vs baseline: 1.5695x; 1.5695x over previous
#include <cuda_runtime.h>
#include <cstdint>

// ---------------------------------------------------------------------------
// GIN: 3 layers of { rst = h + segment_sum(h[src], dst); h = MLP2(rst) }
// N=100000, E=1600000, D=128.
//   - CSR build (3 launches): hist, single-block scan, fill(+deg re-zero)
//   - k_agg: standalone gather (warp/node, high occupancy), batch-8 edge
//     loads + packed add.rn.f32x2 accumulation (bitcast, no movs)
//   - k_mlp: R4-proven fused 2-GEMM MLP, FFMA2, 512 thr, TILE 128
//   - last layer folded: W12 = W1@W2, b12 = b1@W2 + b2 -> single GEMM
// ---------------------------------------------------------------------------

#define DIM 128
#define MAXN 100000
#define MAXE 1600000
#define TILE_M 128
#define SA_PITCH 132
#define MLP_THREADS 512
#define MLP_SMEM_FLOATS (128 * 128 + TILE_M * SA_PITCH)
#define MLP_SMEM_BYTES (MLP_SMEM_FLOATS * 4)

typedef unsigned long long u64;

// scratch (device globals; zero-initialized at load)
__device__ int   g_deg[MAXN];
__device__ int   g_rowptr[MAXN + 1];
__device__ int   g_cursor[MAXN];
__device__ int   g_col[MAXE];
__device__ __align__(16) float g_rst[(size_t)MAXN * DIM];
__device__ __align__(16) float g_hA [(size_t)MAXN * DIM];
__device__ __align__(16) float g_hB [(size_t)MAXN * DIM];
__device__ __align__(16) float g_W12[DIM * DIM];
__device__ __align__(16) float g_b12[DIM];

// ------------------------- f32x2 helpers ------------------------------------

__device__ __forceinline__ u64 pack2(float x, float y) {
    u64 r;
    asm("mov.b64 %0, {%1, %2};" : "=l"(r) : "f"(x), "f"(y));
    return r;
}
__device__ __forceinline__ void unpack2(u64 v, float& x, float& y) {
    asm("mov.b64 {%0, %1}, %2;" : "=f"(x), "=f"(y) : "l"(v));
}
__device__ __forceinline__ void fma2(u64& d, u64 a, u64 b) {
    asm("fma.rn.f32x2 %0, %1, %2, %0;" : "+l"(d) : "l"(a), "l"(b));
}
__device__ __forceinline__ u64 add2(u64 a, u64 b) {
    u64 r;
    asm("add.rn.f32x2 %0, %1, %2;" : "=l"(r) : "l"(a), "l"(b));
    return r;
}

// -------------------------- CSR build ---------------------------------------

__global__ void k_hist(const int* __restrict__ dst, int e) {
    int i = blockIdx.x * blockDim.x + threadIdx.x;
    if (i < e) atomicAdd(&g_deg[dst[i]], 1);
}

__global__ void __launch_bounds__(1024) k_scan1(int n, int e) {
    __shared__ int s[1024];
    const int tid = threadIdx.x;
    int carry = 0;
    const int CH = 1024 * 8;
    for (int base = 0; base < n; base += CH) {
        int v[8];
        int run = 0;
#pragma unroll
        for (int j = 0; j < 8; ++j) {
            int idx = base + tid * 8 + j;
            int t = (idx < n) ? g_deg[idx] : 0;
            v[j] = run;
            run += t;
        }
        s[tid] = run;
        __syncthreads();
        int tot = run;
        for (int off = 1; off < 1024; off <<= 1) {
            int add = (tid >= off) ? s[tid - off] : 0;
            __syncthreads();
            s[tid] += add;
            __syncthreads();
        }
        int excl = carry + s[tid] - tot;
#pragma unroll
        for (int j = 0; j < 8; ++j) {
            int idx = base + tid * 8 + j;
            if (idx < n) {
                int r = excl + v[j];
                g_rowptr[idx] = r;
                g_cursor[idx] = r;
            }
        }
        carry += s[1023];
        __syncthreads();
    }
    if (tid == 0) g_rowptr[n] = e;
}

__global__ void k_fill(const int* __restrict__ src, const int* __restrict__ dst,
                       int e, int n) {
    int i = blockIdx.x * blockDim.x + threadIdx.x;
    if (i < n) g_deg[i] = 0;     // re-zero for next graph replay
    if (i < e) {
        int d = dst[i];
        int pos = atomicAdd(&g_cursor[d], 1);
        g_col[pos] = src[i];
    }
}

// -------------------- last-layer weight folding ------------------------------

__global__ void k_wbfuse(const float* __restrict__ W1g, const float* __restrict__ W2g,
                         const float* __restrict__ b1g, const float* __restrict__ b2g) {
    __shared__ float row[128];
    int nn = threadIdx.x;
    if (blockIdx.x < 128) {
        int k = blockIdx.x;
        row[nn] = W1g[k * 128 + nn];
        __syncthreads();
        float acc = 0.f;
#pragma unroll 8
        for (int j = 0; j < 128; ++j) acc += row[j] * W2g[j * 128 + nn];
        g_W12[k * 128 + nn] = acc;
    } else {
        row[nn] = b1g[nn];
        __syncthreads();
        float acc = b2g[nn];
#pragma unroll 8
        for (int j = 0; j < 128; ++j) acc += row[j] * W2g[j * 128 + nn];
        g_b12[nn] = acc;
    }
}

// ---------------------- aggregation (gather) ---------------------------------
// warp per node, lane owns one float4; batch-8 edge loads (MLP~8) and packed
// f32x2 adds; float4<->2xu64 via register aliasing (no movs).

__global__ void __launch_bounds__(512) k_agg(const float* __restrict__ hin,
                                             float* __restrict__ rst, int n) {
    int warp = (blockIdx.x * blockDim.x + threadIdx.x) >> 5;
    int lane = threadIdx.x & 31;
    if (warp >= n) return;
    const float4* __restrict__ h4 = (const float4*)hin;

    float4 self = h4[(size_t)warp * 32 + lane];     // (1+eps)=1
    u64 ax = ((u64*)&self)[0];
    u64 ay = ((u64*)&self)[1];

    int i = g_rowptr[warp];
    const int epos = g_rowptr[warp + 1];

    for (; i + 8 <= epos; i += 8) {
        int s0 = g_col[i],     s1 = g_col[i + 1];
        int s2 = g_col[i + 2], s3 = g_col[i + 3];
        int s4 = g_col[i + 4], s5 = g_col[i + 5];
        int s6 = g_col[i + 6], s7 = g_col[i + 7];
        float4 v0 = __ldg(&h4[(size_t)s0 * 32 + lane]);
        float4 v1 = __ldg(&h4[(size_t)s1 * 32 + lane]);
        float4 v2 = __ldg(&h4[(size_t)s2 * 32 + lane]);
        float4 v3 = __ldg(&h4[(size_t)s3 * 32 + lane]);
        float4 v4 = __ldg(&h4[(size_t)s4 * 32 + lane]);
        float4 v5 = __ldg(&h4[(size_t)s5 * 32 + lane]);
        float4 v6 = __ldg(&h4[(size_t)s6 * 32 + lane]);
        float4 v7 = __ldg(&h4[(size_t)s7 * 32 + lane]);
        u64 p0 = add2(((u64*)&v0)[0], ((u64*)&v1)[0]);
        u64 p1 = add2(((u64*)&v2)[0], ((u64*)&v3)[0]);
        u64 p2 = add2(((u64*)&v4)[0], ((u64*)&v5)[0]);
        u64 p3 = add2(((u64*)&v6)[0], ((u64*)&v7)[0]);
        u64 q0 = add2(((u64*)&v0)[1], ((u64*)&v1)[1]);
        u64 q1 = add2(((u64*)&v2)[1], ((u64*)&v3)[1]);
        u64 q2 = add2(((u64*)&v4)[1], ((u64*)&v5)[1]);
        u64 q3 = add2(((u64*)&v6)[1], ((u64*)&v7)[1]);
        ax = add2(ax, add2(add2(p0, p1), add2(p2, p3)));
        ay = add2(ay, add2(add2(q0, q1), add2(q2, q3)));
    }
    if (i + 4 <= epos) {
        int s0 = g_col[i],     s1 = g_col[i + 1];
        int s2 = g_col[i + 2], s3 = g_col[i + 3];
        float4 v0 = __ldg(&h4[(size_t)s0 * 32 + lane]);
        float4 v1 = __ldg(&h4[(size_t)s1 * 32 + lane]);
        float4 v2 = __ldg(&h4[(size_t)s2 * 32 + lane]);
        float4 v3 = __ldg(&h4[(size_t)s3 * 32 + lane]);
        u64 p0 = add2(((u64*)&v0)[0], ((u64*)&v1)[0]);
        u64 p1 = add2(((u64*)&v2)[0], ((u64*)&v3)[0]);
        u64 q0 = add2(((u64*)&v0)[1], ((u64*)&v1)[1]);
        u64 q1 = add2(((u64*)&v2)[1], ((u64*)&v3)[1]);
        ax = add2(ax, add2(p0, p1));
        ay = add2(ay, add2(q0, q1));
        i += 4;
    }
    for (; i < epos; ++i) {
        int sn = g_col[i];
        float4 v = __ldg(&h4[(size_t)sn * 32 + lane]);
        ax = add2(ax, ((u64*)&v)[0]);
        ay = add2(ay, ((u64*)&v)[1]);
    }

    ulonglong2 o;
    o.x = ax; o.y = ay;
    ((ulonglong2*)rst)[(size_t)warp * 32 + lane] = o;
}

// ---------------------- fused 2-GEMM MLP (FFMA2) -----------------------------
// out = relu( relu(A @ W1 + b1) @ W2 + b2 ).  512 threads, TILE 128,
// micro-tile 8 rows x 4 cols, packed f32x2 accumulators.  (R4-proven.)

__global__ void __launch_bounds__(MLP_THREADS, 1)
k_mlp(const float* __restrict__ A,
      const float* __restrict__ W1, const float* __restrict__ b1,
      const float* __restrict__ W2, const float* __restrict__ b2,
      float* __restrict__ out, int n) {
    extern __shared__ float smem[];
    float* sW = smem;                 // 128*128
    float* sA = sW + 128 * 128;       // 128*SA_PITCH

    const int tid  = threadIdx.x;
    const int row0 = blockIdx.x * TILE_M;

    {
        const float4* w4 = (const float4*)W1;
        float4* s4 = (float4*)sW;
#pragma unroll
        for (int it = 0; it < 8; ++it) s4[tid + it * 512] = w4[tid + it * 512];
    }
    {
#pragma unroll
        for (int it = 0; it < 8; ++it) {
            int idx = tid + it * 512;       // 0..4095
            int r   = idx >> 5;
            int kq  = idx & 31;
            int rg  = row0 + r;
            float4 f = (rg < n) ? ((const float4*)A)[(size_t)rg * 32 + kq]
                                : make_float4(0.f, 0.f, 0.f, 0.f);
            *(float4*)&sA[r * SA_PITCH + kq * 4] = f;
        }
    }
    __syncthreads();

    const int trow = tid >> 5;   // 0..15 -> rows trow*8..+7
    const int tcol = tid & 31;   // 0..31 -> cols tcol*4..+3
    const int r0   = trow * 8;
    const int c0   = tcol * 4;

    u64 acc[8][2];

    // ---- phase 1: h1 = relu(A @ W1 + b1) ----
    {
        u64 bb0 = pack2(b1[c0],     b1[c0 + 1]);
        u64 bb1 = pack2(b1[c0 + 2], b1[c0 + 3]);
#pragma unroll
        for (int i = 0; i < 8; ++i) { acc[i][0] = bb0; acc[i][1] = bb1; }
    }
#pragma unroll 1
    for (int k0 = 0; k0 < 128; k0 += 4) {
        float4 a4[8];
#pragma unroll
        for (int i = 0; i < 8; ++i)
            a4[i] = *(const float4*)&sA[(r0 + i) * SA_PITCH + k0];
#pragma unroll
        for (int kk = 0; kk < 4; ++kk) {
            ulonglong2 w = *(const ulonglong2*)&sW[(k0 + kk) * 128 + c0];
#pragma unroll
            for (int i = 0; i < 8; ++i) {
                float av = ((const float*)&a4[i])[kk];
                u64 aa = pack2(av, av);
                fma2(acc[i][0], aa, w.x);
                fma2(acc[i][1], aa, w.y);
            }
        }
    }
    __syncthreads();

    // h1 -> sA (relu), W2 -> sW
#pragma unroll
    for (int i = 0; i < 8; ++i) {
#pragma unroll
        for (int p = 0; p < 2; ++p) {
            float x, y;
            unpack2(acc[i][p], x, y);
            x = fmaxf(x, 0.f); y = fmaxf(y, 0.f);
            *(u64*)&sA[(r0 + i) * SA_PITCH + c0 + 2 * p] = pack2(x, y);
        }
    }
    {
        const float4* w4 = (const float4*)W2;
        float4* s4 = (float4*)sW;
#pragma unroll
        for (int it = 0; it < 8; ++it) s4[tid + it * 512] = w4[tid + it * 512];
    }
    __syncthreads();

    // ---- phase 2: out = relu(h1 @ W2 + b2) ----
    {
        u64 bb0 = pack2(b2[c0],     b2[c0 + 1]);
        u64 bb1 = pack2(b2[c0 + 2], b2[c0 + 3]);
#pragma unroll
        for (int i = 0; i < 8; ++i) { acc[i][0] = bb0; acc[i][1] = bb1; }
    }
#pragma unroll 1
    for (int k0 = 0; k0 < 128; k0 += 4) {
        float4 a4[8];
#pragma unroll
        for (int i = 0; i < 8; ++i)
            a4[i] = *(const float4*)&sA[(r0 + i) * SA_PITCH + k0];
#pragma unroll
        for (int kk = 0; kk < 4; ++kk) {
            ulonglong2 w = *(const ulonglong2*)&sW[(k0 + kk) * 128 + c0];
#pragma unroll
            for (int i = 0; i < 8; ++i) {
                float av = ((const float*)&a4[i])[kk];
                u64 aa = pack2(av, av);
                fma2(acc[i][0], aa, w.x);
                fma2(acc[i][1], aa, w.y);
            }
        }
    }

#pragma unroll
    for (int i = 0; i < 8; ++i) {
        int rg = row0 + r0 + i;
        if (rg < n) {
            float x0, y0, x1, y1;
            unpack2(acc[i][0], x0, y0);
            unpack2(acc[i][1], x1, y1);
            x0 = fmaxf(x0, 0.f); y0 = fmaxf(y0, 0.f);
            x1 = fmaxf(x1, 0.f); y1 = fmaxf(y1, 0.f);
            ((float4*)out)[(size_t)rg * 32 + tcol] = make_float4(x0, y0, x1, y1);
        }
    }
}

// ---------------------- last layer: single folded GEMM -----------------------
// out = A @ W12 + b12  (no relu)

__global__ void __launch_bounds__(MLP_THREADS, 1)
k_mlp1(const float* __restrict__ A, float* __restrict__ out, int n) {
    extern __shared__ float smem[];
    float* sW = smem;
    float* sA = sW + 128 * 128;

    const int tid  = threadIdx.x;
    const int row0 = blockIdx.x * TILE_M;

    {
        const float4* w4 = (const float4*)g_W12;
        float4* s4 = (float4*)sW;
#pragma unroll
        for (int it = 0; it < 8; ++it) s4[tid + it * 512] = w4[tid + it * 512];
    }
    {
#pragma unroll
        for (int it = 0; it < 8; ++it) {
            int idx = tid + it * 512;
            int r   = idx >> 5;
            int kq  = idx & 31;
            int rg  = row0 + r;
            float4 f = (rg < n) ? ((const float4*)A)[(size_t)rg * 32 + kq]
                                : make_float4(0.f, 0.f, 0.f, 0.f);
            *(float4*)&sA[r * SA_PITCH + kq * 4] = f;
        }
    }
    __syncthreads();

    const int trow = tid >> 5;
    const int tcol = tid & 31;
    const int r0   = trow * 8;
    const int c0   = tcol * 4;

    u64 acc[8][2];
    {
        u64 bb0 = pack2(g_b12[c0],     g_b12[c0 + 1]);
        u64 bb1 = pack2(g_b12[c0 + 2], g_b12[c0 + 3]);
#pragma unroll
        for (int i = 0; i < 8; ++i) { acc[i][0] = bb0; acc[i][1] = bb1; }
    }
#pragma unroll 1
    for (int k0 = 0; k0 < 128; k0 += 4) {
        float4 a4[8];
#pragma unroll
        for (int i = 0; i < 8; ++i)
            a4[i] = *(const float4*)&sA[(r0 + i) * SA_PITCH + k0];
#pragma unroll
        for (int kk = 0; kk < 4; ++kk) {
            ulonglong2 w = *(const ulonglong2*)&sW[(k0 + kk) * 128 + c0];
#pragma unroll
            for (int i = 0; i < 8; ++i) {
                float av = ((const float*)&a4[i])[kk];
                u64 aa = pack2(av, av);
                fma2(acc[i][0], aa, w.x);
                fma2(acc[i][1], aa, w.y);
            }
        }
    }

#pragma unroll
    for (int i = 0; i < 8; ++i) {
        int rg = row0 + r0 + i;
        if (rg < n) {
            float x0, y0, x1, y1;
            unpack2(acc[i][0], x0, y0);
            unpack2(acc[i][1], x1, y1);
            ((float4*)out)[(size_t)rg * 32 + tcol] = make_float4(x0, y0, x1, y1);
        }
    }
}

// ---------------------------- host ------------------------------------------

extern "C" void kernel_launch(void* const* d_in, const int* in_sizes, int n_in,
                              void* d_out, int out_size) {
    const float* feat = (const float*)d_in[0];
    const float* W1   = (const float*)d_in[1];
    const float* b1   = (const float*)d_in[2];
    const float* W2   = (const float*)d_in[3];
    const float* b2   = (const float*)d_in[4];
    const int*   src  = (const int*)d_in[5];
    const int*   dst  = (const int*)d_in[6];

    const int n = in_sizes[0] / DIM;
    const int e = in_sizes[5];

    cudaFuncSetAttribute((const void*)k_mlp,
                         cudaFuncAttributeMaxDynamicSharedMemorySize, MLP_SMEM_BYTES);
    cudaFuncSetAttribute((const void*)k_mlp1,
                         cudaFuncAttributeMaxDynamicSharedMemorySize, MLP_SMEM_BYTES);

    float *rst, *hA, *hB;
    cudaGetSymbolAddress((void**)&rst, g_rst);
    cudaGetSymbolAddress((void**)&hA,  g_hA);
    cudaGetSymbolAddress((void**)&hB,  g_hB);

    const int aggBlocks = (n + 15) / 16;               // 16 warps / block
    const int mlpBlocks = (n + TILE_M - 1) / TILE_M;

    // ---- CSR build + weight folding ----
    k_hist<<<(e + 255) / 256, 256>>>(dst, e);                          // 0
    k_scan1<<<1, 1024>>>(n, e);                                        // 1
    k_fill<<<(e + 255) / 256, 256>>>(src, dst, e, n);                  // 2
    k_wbfuse<<<129, 128>>>(W1 + 2 * DIM * DIM, W2 + 2 * DIM * DIM,
                           b1 + 2 * DIM, b2 + 2 * DIM);                // 3

    // ---- layer 0 ----
    k_agg<<<aggBlocks, 512>>>(feat, rst, n);                           // 4
    k_mlp<<<mlpBlocks, MLP_THREADS, MLP_SMEM_BYTES>>>(                 // 5 (ncu)
        rst, W1 + 0 * DIM * DIM, b1 + 0 * DIM, W2 + 0 * DIM * DIM, b2 + 0 * DIM,
        hA, n);
    // ---- layer 1 ----
    k_agg<<<aggBlocks, 512>>>(hA, rst, n);                             // 6
    k_mlp<<<mlpBlocks, MLP_THREADS, MLP_SMEM_BYTES>>>(                 // 7
        rst, W1 + 1 * DIM * DIM, b1 + 1 * DIM, W2 + 1 * DIM * DIM, b2 + 1 * DIM,
        hB, n);
    // ---- layer 2 (folded single GEMM, no relu) ----
    k_agg<<<aggBlocks, 512>>>(hB, rst, n);                             // 8
    k_mlp1<<<mlpBlocks, MLP_THREADS, MLP_SMEM_BYTES>>>(rst, (float*)d_out, n); // 9
}

// round 15
// speedup vs baseline: 1.9205x; 1.2236x over previous
#include <cuda_runtime.h>
#include <cstdint>

// ---------------------------------------------------------------------------
// GIN: 3 layers of { rst = h + segment_sum(h[src], dst); h = MLP2(rst) }
// N=100000, E=1600000, D=128.  All components individually proven:
//   - CSR build: hist, multi-block scan (R8), fill(+deg re-zero)
//   - k_agg: R4's plain gather (warp/node, float4/lane) - near L2 BW floor
//   - k_mlp: R4's fused 2-GEMM FFMA2 MLP (TILE 128, 512 thr)
//   - last layer folded to single GEMM: W12 = W1@W2, b12 = b1@W2 + b2
// ---------------------------------------------------------------------------

#define DIM 128
#define MAXN 100000
#define MAXE 1600000
#define TILE_M 128
#define SA_PITCH 132
#define MLP_THREADS 512
#define MLP_SMEM_FLOATS (128 * 128 + TILE_M * SA_PITCH)
#define MLP_SMEM_BYTES (MLP_SMEM_FLOATS * 4)
#define SCAN_CHUNK 2048
#define MAX_SCAN_BLOCKS 64

typedef unsigned long long u64;

// scratch (device globals; zero-initialized at load; k_fill re-zeros g_deg)
__device__ int   g_deg[MAXN];
__device__ int   g_rowptr[MAXN + 1];
__device__ int   g_cursor[MAXN];
__device__ int   g_col[MAXE];
__device__ int   g_bsum[MAX_SCAN_BLOCKS];
__device__ __align__(16) float g_rst[(size_t)MAXN * DIM];
__device__ __align__(16) float g_hA [(size_t)MAXN * DIM];
__device__ __align__(16) float g_hB [(size_t)MAXN * DIM];
__device__ __align__(16) float g_W12[DIM * DIM];
__device__ __align__(16) float g_b12[DIM];

// ------------------------- f32x2 helpers ------------------------------------

__device__ __forceinline__ u64 pack2(float x, float y) {
    u64 r;
    asm("mov.b64 %0, {%1, %2};" : "=l"(r) : "f"(x), "f"(y));
    return r;
}
__device__ __forceinline__ void unpack2(u64 v, float& x, float& y) {
    asm("mov.b64 {%0, %1}, %2;" : "=f"(x), "=f"(y) : "l"(v));
}
__device__ __forceinline__ void fma2(u64& d, u64 a, u64 b) {
    asm("fma.rn.f32x2 %0, %1, %2, %0;" : "+l"(d) : "l"(a), "l"(b));
}

// -------------------------- CSR build (R8-proven) ----------------------------

__global__ void k_hist(const int* __restrict__ dst, int e) {
    int i = blockIdx.x * blockDim.x + threadIdx.x;
    if (i < e) atomicAdd(&g_deg[dst[i]], 1);
}

__global__ void k_scan_reduce(int n) {
    __shared__ int s[256];
    int tid = threadIdx.x;
    int base = blockIdx.x * SCAN_CHUNK + tid * 8;
    int tot = 0;
#pragma unroll
    for (int j = 0; j < 8; ++j) {
        int idx = base + j;
        tot += (idx < n) ? g_deg[idx] : 0;
    }
    s[tid] = tot;
    __syncthreads();
    for (int off = 128; off > 0; off >>= 1) {
        if (tid < off) s[tid] += s[tid + off];
        __syncthreads();
    }
    if (tid == 0) g_bsum[blockIdx.x] = s[0];
}

__global__ void k_scan_bsum(int nb, int e, int n) {
    __shared__ int s[64];
    int t = threadIdx.x;
    int v = (t < nb) ? g_bsum[t] : 0;
    s[t] = v;
    __syncthreads();
    for (int off = 1; off < 64; off <<= 1) {
        int a = (t >= off) ? s[t - off] : 0;
        __syncthreads();
        s[t] += a;
        __syncthreads();
    }
    if (t < nb) g_bsum[t] = s[t] - v;
    if (t == 0) g_rowptr[n] = e;
}

__global__ void k_scan_final(int n) {
    __shared__ int s[256];
    int tid = threadIdx.x;
    int base = blockIdx.x * SCAN_CHUNK + tid * 8;
    int v[8];
    int run = 0;
#pragma unroll
    for (int j = 0; j < 8; ++j) {
        int idx = base + j;
        int t = (idx < n) ? g_deg[idx] : 0;
        v[j] = run;
        run += t;
    }
    int tot = run;
    s[tid] = tot;
    __syncthreads();
    for (int off = 1; off < 256; off <<= 1) {
        int add = (tid >= off) ? s[tid - off] : 0;
        __syncthreads();
        s[tid] += add;
        __syncthreads();
    }
    int texcl = s[tid] - tot;
    int pref = g_bsum[blockIdx.x] + texcl;
#pragma unroll
    for (int j = 0; j < 8; ++j) {
        int idx = base + j;
        if (idx < n) {
            int r = pref + v[j];
            g_rowptr[idx] = r;
            g_cursor[idx] = r;
        }
    }
}

// bucket fill; re-zeroes g_deg for the next graph replay
__global__ void k_fill(const int* __restrict__ src, const int* __restrict__ dst,
                       int e, int n) {
    int i = blockIdx.x * blockDim.x + threadIdx.x;
    if (i < n) g_deg[i] = 0;
    if (i < e) {
        int d = dst[i];
        int pos = atomicAdd(&g_cursor[d], 1);
        g_col[pos] = src[i];
    }
}

// -------------------- last-layer weight folding ------------------------------

__global__ void k_wbfuse(const float* __restrict__ W1g, const float* __restrict__ W2g,
                         const float* __restrict__ b1g, const float* __restrict__ b2g) {
    __shared__ float row[128];
    int nn = threadIdx.x;
    if (blockIdx.x < 128) {
        int k = blockIdx.x;
        row[nn] = W1g[k * 128 + nn];
        __syncthreads();
        float acc = 0.f;
#pragma unroll 8
        for (int j = 0; j < 128; ++j) acc += row[j] * W2g[j * 128 + nn];
        g_W12[k * 128 + nn] = acc;
    } else {
        row[nn] = b1g[nn];
        __syncthreads();
        float acc = b2g[nn];
#pragma unroll 8
        for (int j = 0; j < 128; ++j) acc += row[j] * W2g[j * 128 + nn];
        g_b12[nn] = acc;
    }
}

// ---------------------- aggregation (R4-proven) ------------------------------
// warp per node, lane owns one float4 of the 128-dim row. EPS = 0.

__global__ void __launch_bounds__(256) k_agg(const float* __restrict__ hin,
                                             float* __restrict__ rst, int n) {
    int warp = (blockIdx.x * blockDim.x + threadIdx.x) >> 5;
    int lane = threadIdx.x & 31;
    if (warp >= n) return;
    const float4* __restrict__ h4 = (const float4*)hin;
    float4 a = h4[(size_t)warp * 32 + lane];  // self, (1+eps)=1
    int s = g_rowptr[warp];
    int epos = g_rowptr[warp + 1];
    for (int i = s; i < epos; ++i) {
        int sn = g_col[i];
        float4 v = __ldg(&h4[(size_t)sn * 32 + lane]);
        a.x += v.x; a.y += v.y; a.z += v.z; a.w += v.w;
    }
    ((float4*)rst)[(size_t)warp * 32 + lane] = a;
}

// ---------------------- fused 2-GEMM MLP (R4-proven) -------------------------
// out = relu( relu(A @ W1 + b1) @ W2 + b2 ).  512 threads, TILE 128,
// micro-tile 8 rows x 4 cols, packed f32x2 accumulators.

__global__ void __launch_bounds__(MLP_THREADS, 1)
k_mlp(const float* __restrict__ A,
      const float* __restrict__ W1, const float* __restrict__ b1,
      const float* __restrict__ W2, const float* __restrict__ b2,
      float* __restrict__ out, int n) {
    extern __shared__ float smem[];
    float* sW = smem;                 // 128*128
    float* sA = sW + 128 * 128;       // 128*SA_PITCH

    const int tid  = threadIdx.x;
    const int row0 = blockIdx.x * TILE_M;

    {
        const float4* w4 = (const float4*)W1;
        float4* s4 = (float4*)sW;
#pragma unroll
        for (int it = 0; it < 8; ++it) s4[tid + it * 512] = w4[tid + it * 512];
    }
    {
#pragma unroll
        for (int it = 0; it < 8; ++it) {
            int idx = tid + it * 512;       // 0..4095
            int r   = idx >> 5;
            int kq  = idx & 31;
            int rg  = row0 + r;
            float4 f = (rg < n) ? ((const float4*)A)[(size_t)rg * 32 + kq]
                                : make_float4(0.f, 0.f, 0.f, 0.f);
            *(float4*)&sA[r * SA_PITCH + kq * 4] = f;
        }
    }
    __syncthreads();

    const int trow = tid >> 5;   // 0..15 -> rows trow*8..+7
    const int tcol = tid & 31;   // 0..31 -> cols tcol*4..+3
    const int r0   = trow * 8;
    const int c0   = tcol * 4;

    u64 acc[8][2];

    // ---- phase 1: h1 = relu(A @ W1 + b1) ----
    {
        u64 bb0 = pack2(b1[c0],     b1[c0 + 1]);
        u64 bb1 = pack2(b1[c0 + 2], b1[c0 + 3]);
#pragma unroll
        for (int i = 0; i < 8; ++i) { acc[i][0] = bb0; acc[i][1] = bb1; }
    }
#pragma unroll 1
    for (int k0 = 0; k0 < 128; k0 += 4) {
        float4 a4[8];
#pragma unroll
        for (int i = 0; i < 8; ++i)
            a4[i] = *(const float4*)&sA[(r0 + i) * SA_PITCH + k0];
#pragma unroll
        for (int kk = 0; kk < 4; ++kk) {
            ulonglong2 w = *(const ulonglong2*)&sW[(k0 + kk) * 128 + c0];
#pragma unroll
            for (int i = 0; i < 8; ++i) {
                float av = ((const float*)&a4[i])[kk];
                u64 aa = pack2(av, av);
                fma2(acc[i][0], aa, w.x);
                fma2(acc[i][1], aa, w.y);
            }
        }
    }
    __syncthreads();

    // h1 -> sA (relu), W2 -> sW
#pragma unroll
    for (int i = 0; i < 8; ++i) {
#pragma unroll
        for (int p = 0; p < 2; ++p) {
            float x, y;
            unpack2(acc[i][p], x, y);
            x = fmaxf(x, 0.f); y = fmaxf(y, 0.f);
            *(u64*)&sA[(r0 + i) * SA_PITCH + c0 + 2 * p] = pack2(x, y);
        }
    }
    {
        const float4* w4 = (const float4*)W2;
        float4* s4 = (float4*)sW;
#pragma unroll
        for (int it = 0; it < 8; ++it) s4[tid + it * 512] = w4[tid + it * 512];
    }
    __syncthreads();

    // ---- phase 2: out = relu(h1 @ W2 + b2) ----
    {
        u64 bb0 = pack2(b2[c0],     b2[c0 + 1]);
        u64 bb1 = pack2(b2[c0 + 2], b2[c0 + 3]);
#pragma unroll
        for (int i = 0; i < 8; ++i) { acc[i][0] = bb0; acc[i][1] = bb1; }
    }
#pragma unroll 1
    for (int k0 = 0; k0 < 128; k0 += 4) {
        float4 a4[8];
#pragma unroll
        for (int i = 0; i < 8; ++i)
            a4[i] = *(const float4*)&sA[(r0 + i) * SA_PITCH + k0];
#pragma unroll
        for (int kk = 0; kk < 4; ++kk) {
            ulonglong2 w = *(const ulonglong2*)&sW[(k0 + kk) * 128 + c0];
#pragma unroll
            for (int i = 0; i < 8; ++i) {
                float av = ((const float*)&a4[i])[kk];
                u64 aa = pack2(av, av);
                fma2(acc[i][0], aa, w.x);
                fma2(acc[i][1], aa, w.y);
            }
        }
    }

#pragma unroll
    for (int i = 0; i < 8; ++i) {
        int rg = row0 + r0 + i;
        if (rg < n) {
            float x0, y0, x1, y1;
            unpack2(acc[i][0], x0, y0);
            unpack2(acc[i][1], x1, y1);
            x0 = fmaxf(x0, 0.f); y0 = fmaxf(y0, 0.f);
            x1 = fmaxf(x1, 0.f); y1 = fmaxf(y1, 0.f);
            ((float4*)out)[(size_t)rg * 32 + tcol] = make_float4(x0, y0, x1, y1);
        }
    }
}

// ---------------------- last layer: single folded GEMM -----------------------
// out = A @ W12 + b12  (no relu)

__global__ void __launch_bounds__(MLP_THREADS, 1)
k_mlp1(const float* __restrict__ A, float* __restrict__ out, int n) {
    extern __shared__ float smem[];
    float* sW = smem;
    float* sA = sW + 128 * 128;

    const int tid  = threadIdx.x;
    const int row0 = blockIdx.x * TILE_M;

    {
        const float4* w4 = (const float4*)g_W12;
        float4* s4 = (float4*)sW;
#pragma unroll
        for (int it = 0; it < 8; ++it) s4[tid + it * 512] = w4[tid + it * 512];
    }
    {
#pragma unroll
        for (int it = 0; it < 8; ++it) {
            int idx = tid + it * 512;
            int r   = idx >> 5;
            int kq  = idx & 31;
            int rg  = row0 + r;
            float4 f = (rg < n) ? ((const float4*)A)[(size_t)rg * 32 + kq]
                                : make_float4(0.f, 0.f, 0.f, 0.f);
            *(float4*)&sA[r * SA_PITCH + kq * 4] = f;
        }
    }
    __syncthreads();

    const int trow = tid >> 5;
    const int tcol = tid & 31;
    const int r0   = trow * 8;
    const int c0   = tcol * 4;

    u64 acc[8][2];
    {
        u64 bb0 = pack2(g_b12[c0],     g_b12[c0 + 1]);
        u64 bb1 = pack2(g_b12[c0 + 2], g_b12[c0 + 3]);
#pragma unroll
        for (int i = 0; i < 8; ++i) { acc[i][0] = bb0; acc[i][1] = bb1; }
    }
#pragma unroll 1
    for (int k0 = 0; k0 < 128; k0 += 4) {
        float4 a4[8];
#pragma unroll
        for (int i = 0; i < 8; ++i)
            a4[i] = *(const float4*)&sA[(r0 + i) * SA_PITCH + k0];
#pragma unroll
        for (int kk = 0; kk < 4; ++kk) {
            ulonglong2 w = *(const ulonglong2*)&sW[(k0 + kk) * 128 + c0];
#pragma unroll
            for (int i = 0; i < 8; ++i) {
                float av = ((const float*)&a4[i])[kk];
                u64 aa = pack2(av, av);
                fma2(acc[i][0], aa, w.x);
                fma2(acc[i][1], aa, w.y);
            }
        }
    }

#pragma unroll
    for (int i = 0; i < 8; ++i) {
        int rg = row0 + r0 + i;
        if (rg < n) {
            float x0, y0, x1, y1;
            unpack2(acc[i][0], x0, y0);
            unpack2(acc[i][1], x1, y1);
            ((float4*)out)[(size_t)rg * 32 + tcol] = make_float4(x0, y0, x1, y1);
        }
    }
}

// ---------------------------- host ------------------------------------------

extern "C" void kernel_launch(void* const* d_in, const int* in_sizes, int n_in,
                              void* d_out, int out_size) {
    const float* feat = (const float*)d_in[0];
    const float* W1   = (const float*)d_in[1];
    const float* b1   = (const float*)d_in[2];
    const float* W2   = (const float*)d_in[3];
    const float* b2   = (const float*)d_in[4];
    const int*   src  = (const int*)d_in[5];
    const int*   dst  = (const int*)d_in[6];

    const int n = in_sizes[0] / DIM;
    const int e = in_sizes[5];

    cudaFuncSetAttribute((const void*)k_mlp,
                         cudaFuncAttributeMaxDynamicSharedMemorySize, MLP_SMEM_BYTES);
    cudaFuncSetAttribute((const void*)k_mlp1,
                         cudaFuncAttributeMaxDynamicSharedMemorySize, MLP_SMEM_BYTES);

    float *rst, *hA, *hB;
    cudaGetSymbolAddress((void**)&rst, g_rst);
    cudaGetSymbolAddress((void**)&hA,  g_hA);
    cudaGetSymbolAddress((void**)&hB,  g_hB);

    const int aggBlocks = (n + 7) / 8;                  // 8 warps / block
    const int mlpBlocks = (n + TILE_M - 1) / TILE_M;
    const int nb = (n + SCAN_CHUNK - 1) / SCAN_CHUNK;

    // ---- CSR build (g_deg zero at load; k_fill re-zeros for replay) ----
    k_hist<<<(e + 255) / 256, 256>>>(dst, e);                          // 0
    k_scan_reduce<<<nb, 256>>>(n);                                     // 1
    k_scan_bsum<<<1, 64>>>(nb, e, n);                                  // 2
    k_scan_final<<<nb, 256>>>(n);                                      // 3
    k_fill<<<(e + 255) / 256, 256>>>(src, dst, e, n);                  // 4

    // ---- layer 0 ----
    k_agg<<<aggBlocks, 256>>>(feat, rst, n);                           // 5 (ncu)
    k_mlp<<<mlpBlocks, MLP_THREADS, MLP_SMEM_BYTES>>>(                 // 6
        rst, W1 + 0 * DIM * DIM, b1 + 0 * DIM, W2 + 0 * DIM * DIM, b2 + 0 * DIM,
        hA, n);
    // fold last-layer weights (independent; anywhere before k_mlp1)
    k_wbfuse<<<129, 128>>>(W1 + 2 * DIM * DIM, W2 + 2 * DIM * DIM,
                           b1 + 2 * DIM, b2 + 2 * DIM);                // 7
    // ---- layer 1 ----
    k_agg<<<aggBlocks, 256>>>(hA, rst, n);                             // 8
    k_mlp<<<mlpBlocks, MLP_THREADS, MLP_SMEM_BYTES>>>(                 // 9
        rst, W1 + 1 * DIM * DIM, b1 + 1 * DIM, W2 + 1 * DIM * DIM, b2 + 1 * DIM,
        hB, n);
    // ---- layer 2 (folded single GEMM, no relu) ----
    k_agg<<<aggBlocks, 256>>>(hB, rst, n);                             // 10
    k_mlp1<<<mlpBlocks, MLP_THREADS, MLP_SMEM_BYTES>>>(rst, (float*)d_out, n); // 11
}